// round 7
// baseline (speedup 1.0000x reference)
#include <cuda_runtime.h>
#include <math.h>

// ---------------------------------------------------------------------------
// ResidualSTU  (B=2, S=1024, D_IN=64, D=512, K=16, KU=3, L=2, M=2, H=2048)
//
// FFT-free restructuring:
//   Up[b,s,k,:]  = sum_{t<=s} phi[s-t,k]            * h[b,t,:]
//   Um[b,s,k,:]  = sum_{t<=s} (-1)^{s-t} phi[s-t,k] * h[b,t,:]
// Even/odd split (halves conv FLOPs):
//   E = conv over even t, O = conv over odd t  ->  Up = E+O, Um = (-1)^s (E-O)
// spec folded into one big projection GEMM; sigma^0.25 folded into conv out;
// ar_u folded into projection tail; residuals folded into epilogues;
// swiglu fused into fc1 epilogue; in_proj/out_proj are tiled GEMMs too.
// Heavy GEMMs: 128-row tiles, 8-wide microtiles, packed fma.rn.f32x2 (FFMA2),
// double-buffered smem pipeline (1 barrier per k-tile, gmem latency hidden).
// ---------------------------------------------------------------------------

#define BB   2
#define SS   1024
#define DIN  64
#define DD   512
#define KK   16
#define KUU  3
#define LL   2
#define MM   2
#define HH   2048
#define J2K  32               // 2*K filters (plus & minus)
#define ROWS (BB*SS)          // 2048
#define CDIM (J2K*DD)         // 16384 contraction dim of projection GEMM
#define EPSV 1e-5f

// -------------------------- device scratch (no allocs allowed) -------------
__device__ float g_x [ROWS*DD];        // residual stream          (4 MB)
__device__ float g_h [ROWS*DD];        // rmsnorm output           (4 MB)
__device__ float g_x2[ROWS*DD];        // x + y_t                  (4 MB)
__device__ float g_Uc[ROWS*CDIM];      // conv outputs (scaled)    (134 MB)
__device__ float g_g [ROWS*HH];        // swiglu output            (16.8 MB)

// -------------------------- f32x2 packed helpers ---------------------------
typedef unsigned long long u64t;

__device__ __forceinline__ u64t pk2(float x, float y) {
    u64t r; asm("mov.b64 %0, {%1,%2};" : "=l"(r) : "f"(x), "f"(y)); return r;
}
__device__ __forceinline__ void fma2(u64t& d, u64t a, u64t b) {
    asm("fma.rn.f32x2 %0, %1, %2, %0;" : "+l"(d) : "l"(a), "l"(b));
}
__device__ __forceinline__ float2 up2(u64t v) {
    float2 r; asm("mov.b64 {%0,%1}, %2;" : "=f"(r.x), "=f"(r.y) : "l"(v)); return r;
}

// -------------------------- rmsnorm ----------------------------------------
__global__ void k_rmsnorm(const float* __restrict__ w) {
    int row = blockIdx.x;
    int tid = threadIdx.x;                    // 256 threads
    const float* xr = g_x + row*DD;
    float v0 = xr[tid], v1 = xr[tid + 256];
    float s = v0*v0 + v1*v1;
    __shared__ float red[8];
    #pragma unroll
    for (int off = 16; off; off >>= 1) s += __shfl_xor_sync(0xffffffffu, s, off);
    if ((tid & 31) == 0) red[tid >> 5] = s;
    __syncthreads();
    if (tid < 8) {
        float t = red[tid];
        #pragma unroll
        for (int off = 4; off; off >>= 1) t += __shfl_xor_sync(0xffu, t, off);
        if (tid == 0) red[0] = t;
    }
    __syncthreads();
    float scale = rsqrtf(red[0] * (1.f/DD) + EPSV);
    g_h[row*DD + tid]       = v0*scale*w[tid];
    g_h[row*DD + tid + 256] = v1*scale*w[tid + 256];
}

// -------------------------- causal Toeplitz conv (even/odd fused) ----------
// One block per (b, k): computes BOTH
//   Uc[.., j=k   ] = s4*(E+O)            (plus filter)
//   Uc[.., j=k+16] = s4*(-1)^s*(E-O)     (minus filter)
// Tile: 128 s x 64 d, BK=16, 256 threads, 8x4 microtile x2 parity banks.
__global__ void __launch_bounds__(256) k_conv(const float* __restrict__ phi,
                                              const float* __restrict__ sigma) {
    int d0 = blockIdx.x * 64;
    int s0 = blockIdx.y * 128;
    int bj = blockIdx.z;                      // 0..31
    int b  = bj >> 4;
    int k  = bj & 15;

    __shared__ float sh_h[2][16][64];
    __shared__ float sh_c[2][144];            // plus-filter window only

    int tid = threadIdx.x;
    int tx = tid & 15, ty = tid >> 4;
    int hr = tid >> 4, hc = (tid & 15) * 4;   // h-tile loader coords
    u64t accE[4][4], accO[4][4];
    #pragma unroll
    for (int p = 0; p < 4; p++)
        #pragma unroll
        for (int c = 0; c < 4; c++) { accE[p][c] = 0ull; accO[p][c] = 0ull; }

    const float* hb = g_h + b*SS*DD;
    int NT = (s0 + 128) >> 4;                 // causal: t < s0+128

    float4 h_reg; float c_reg = 0.f;
    // ---- fetch tile 0
    h_reg = *reinterpret_cast<const float4*>(&hb[hr*DD + d0 + hc]);
    if (tid < 144) {
        int tau = s0 - 15 + tid;
        c_reg = (tau >= 0 && tau < SS) ? phi[tau*KK + k] : 0.f;
    }
    *reinterpret_cast<float4*>(&sh_h[0][hr][hc]) = h_reg;
    if (tid < 144) sh_c[0][tid] = c_reg;
    __syncthreads();

    int cur = 0;
    for (int kt = 0; kt < NT; kt++) {
        if (kt + 1 < NT) {                    // prefetch tile kt+1
            int t0 = (kt + 1) << 4;
            h_reg = *reinterpret_cast<const float4*>(&hb[(t0+hr)*DD + d0 + hc]);
            if (tid < 144) {
                int tau = s0 - t0 - 15 + tid;
                c_reg = (tau >= 0 && tau < SS) ? phi[tau*KK + k] : 0.f;
            }
        }
        #pragma unroll
        for (int tt = 0; tt < 16; tt++) {     // t = kt*16 + tt; parity = tt&1
            int base = ty*8 + 15 - tt;        // sh_c idx = row - tt + 15
            u64t a0 = pk2(sh_c[cur][base+0], sh_c[cur][base+1]);
            u64t a1 = pk2(sh_c[cur][base+2], sh_c[cur][base+3]);
            u64t a2 = pk2(sh_c[cur][base+4], sh_c[cur][base+5]);
            u64t a3 = pk2(sh_c[cur][base+6], sh_c[cur][base+7]);
            float4 bv = *reinterpret_cast<const float4*>(&sh_h[cur][tt][tx*4]);
            u64t b0 = pk2(bv.x, bv.x), b1 = pk2(bv.y, bv.y);
            u64t b2 = pk2(bv.z, bv.z), b3 = pk2(bv.w, bv.w);
            if ((tt & 1) == 0) {              // compile-time after unroll
                fma2(accE[0][0], a0, b0); fma2(accE[0][1], a0, b1);
                fma2(accE[0][2], a0, b2); fma2(accE[0][3], a0, b3);
                fma2(accE[1][0], a1, b0); fma2(accE[1][1], a1, b1);
                fma2(accE[1][2], a1, b2); fma2(accE[1][3], a1, b3);
                fma2(accE[2][0], a2, b0); fma2(accE[2][1], a2, b1);
                fma2(accE[2][2], a2, b2); fma2(accE[2][3], a2, b3);
                fma2(accE[3][0], a3, b0); fma2(accE[3][1], a3, b1);
                fma2(accE[3][2], a3, b2); fma2(accE[3][3], a3, b3);
            } else {
                fma2(accO[0][0], a0, b0); fma2(accO[0][1], a0, b1);
                fma2(accO[0][2], a0, b2); fma2(accO[0][3], a0, b3);
                fma2(accO[1][0], a1, b0); fma2(accO[1][1], a1, b1);
                fma2(accO[1][2], a1, b2); fma2(accO[1][3], a1, b3);
                fma2(accO[2][0], a2, b0); fma2(accO[2][1], a2, b1);
                fma2(accO[2][2], a2, b2); fma2(accO[2][3], a2, b3);
                fma2(accO[3][0], a3, b0); fma2(accO[3][1], a3, b1);
                fma2(accO[3][2], a3, b2); fma2(accO[3][3], a3, b3);
            }
        }
        if (kt + 1 < NT) {
            int nxt = cur ^ 1;
            *reinterpret_cast<float4*>(&sh_h[nxt][hr][hc]) = h_reg;
            if (tid < 144) sh_c[nxt][tid] = c_reg;
            __syncthreads();
            cur = nxt;
        }
    }

    float s4 = sqrtf(sqrtf(sigma[k]));        // sigma^0.25 folded here
    #pragma unroll
    for (int p = 0; p < 4; p++) {
        float2 e0 = up2(accE[p][0]), e1 = up2(accE[p][1]);
        float2 e2 = up2(accE[p][2]), e3 = up2(accE[p][3]);
        float2 o0 = up2(accO[p][0]), o1 = up2(accO[p][1]);
        float2 o2 = up2(accO[p][2]), o3 = up2(accO[p][3]);
        int sA = s0 + ty*8 + 2*p;             // even row; sA+1 odd
        // Up = s4*(E+O)
        float4 up_lo = make_float4((e0.x+o0.x)*s4, (e1.x+o1.x)*s4,
                                   (e2.x+o2.x)*s4, (e3.x+o3.x)*s4);
        float4 up_hi = make_float4((e0.y+o0.y)*s4, (e1.y+o1.y)*s4,
                                   (e2.y+o2.y)*s4, (e3.y+o3.y)*s4);
        // Um = s4*(-1)^s*(E-O): + on even rows (.x), - on odd rows (.y)
        float4 um_lo = make_float4((e0.x-o0.x)*s4, (e1.x-o1.x)*s4,
                                   (e2.x-o2.x)*s4, (e3.x-o3.x)*s4);
        float4 um_hi = make_float4((o0.y-e0.y)*s4, (o1.y-e1.y)*s4,
                                   (o2.y-e2.y)*s4, (o3.y-e3.y)*s4);
        size_t rl = ((size_t)(b*SS + sA    )*J2K);
        size_t rh = ((size_t)(b*SS + sA + 1)*J2K);
        *reinterpret_cast<float4*>(&g_Uc[(rl + k     )*DD + d0 + tx*4]) = up_lo;
        *reinterpret_cast<float4*>(&g_Uc[(rh + k     )*DD + d0 + tx*4]) = up_hi;
        *reinterpret_cast<float4*>(&g_Uc[(rl + k + 16)*DD + d0 + tx*4]) = um_lo;
        *reinterpret_cast<float4*>(&g_Uc[(rh + k + 16)*DD + d0 + tx*4]) = um_hi;
    }
}

// Packed inner: 4 row-pairs from SHA (8B-aligned), 4 broadcast cols from SHW.
#define GEMM_INNER2(SHA, SHW)                                                    \
    _Pragma("unroll")                                                            \
    for (int tt = 0; tt < 16; tt++) {                                            \
        u64t a0 = *reinterpret_cast<const u64t*>(&SHA[tt][ty*8+0]);              \
        u64t a1 = *reinterpret_cast<const u64t*>(&SHA[tt][ty*8+2]);              \
        u64t a2 = *reinterpret_cast<const u64t*>(&SHA[tt][ty*8+4]);              \
        u64t a3 = *reinterpret_cast<const u64t*>(&SHA[tt][ty*8+6]);              \
        float4 w4 = *reinterpret_cast<const float4*>(&SHW[tt][tx*4]);            \
        u64t b0 = pk2(w4.x, w4.x), b1 = pk2(w4.y, w4.y);                         \
        u64t b2 = pk2(w4.z, w4.z), b3 = pk2(w4.w, w4.w);                         \
        fma2(acc2[0][0], a0, b0); fma2(acc2[0][1], a0, b1);                      \
        fma2(acc2[0][2], a0, b2); fma2(acc2[0][3], a0, b3);                      \
        fma2(acc2[1][0], a1, b0); fma2(acc2[1][1], a1, b1);                      \
        fma2(acc2[1][2], a1, b2); fma2(acc2[1][3], a1, b3);                      \
        fma2(acc2[2][0], a2, b0); fma2(acc2[2][1], a2, b1);                      \
        fma2(acc2[2][2], a2, b2); fma2(acc2[2][3], a2, b3);                      \
        fma2(acc2[3][0], a3, b0); fma2(acc2[3][1], a3, b1);                      \
        fma2(acc2[3][2], a3, b2); fma2(acc2[3][3], a3, b3);                      \
    }

// Same inner but accumulating into two banks (Y and G) from two W tiles.
#define GEMM_INNER2_DUAL(SHA, SHWY, SHWG)                                        \
    _Pragma("unroll")                                                            \
    for (int tt = 0; tt < 16; tt++) {                                            \
        u64t a0 = *reinterpret_cast<const u64t*>(&SHA[tt][ty*8+0]);              \
        u64t a1 = *reinterpret_cast<const u64t*>(&SHA[tt][ty*8+2]);              \
        u64t a2 = *reinterpret_cast<const u64t*>(&SHA[tt][ty*8+4]);              \
        u64t a3 = *reinterpret_cast<const u64t*>(&SHA[tt][ty*8+6]);              \
        float4 wy = *reinterpret_cast<const float4*>(&SHWY[tt][tx*4]);           \
        float4 wg = *reinterpret_cast<const float4*>(&SHWG[tt][tx*4]);           \
        u64t y0 = pk2(wy.x, wy.x), y1 = pk2(wy.y, wy.y);                         \
        u64t y2 = pk2(wy.z, wy.z), y3 = pk2(wy.w, wy.w);                         \
        u64t g0 = pk2(wg.x, wg.x), g1 = pk2(wg.y, wg.y);                         \
        u64t g2 = pk2(wg.z, wg.z), g3 = pk2(wg.w, wg.w);                         \
        fma2(accY[0][0], a0, y0); fma2(accY[0][1], a0, y1);                      \
        fma2(accY[0][2], a0, y2); fma2(accY[0][3], a0, y3);                      \
        fma2(accY[1][0], a1, y0); fma2(accY[1][1], a1, y1);                      \
        fma2(accY[1][2], a1, y2); fma2(accY[1][3], a1, y3);                      \
        fma2(accY[2][0], a2, y0); fma2(accY[2][1], a2, y1);                      \
        fma2(accY[2][2], a2, y2); fma2(accY[2][3], a2, y3);                      \
        fma2(accY[3][0], a3, y0); fma2(accY[3][1], a3, y1);                      \
        fma2(accY[3][2], a3, y2); fma2(accY[3][3], a3, y3);                      \
        fma2(accG[0][0], a0, g0); fma2(accG[0][1], a0, g1);                      \
        fma2(accG[0][2], a0, g2); fma2(accG[0][3], a0, g3);                      \
        fma2(accG[1][0], a1, g0); fma2(accG[1][1], a1, g1);                      \
        fma2(accG[1][2], a1, g2); fma2(accG[1][3], a1, g3);                      \
        fma2(accG[2][0], a2, g0); fma2(accG[2][1], a2, g1);                      \
        fma2(accG[2][2], a2, g2); fma2(accG[2][3], a2, g3);                      \
        fma2(accG[3][0], a3, g0); fma2(accG[3][1], a3, g1);                      \
        fma2(accG[3][2], a3, g2); fma2(accG[3][3], a3, g3);                      \
    }

#define ZERO_ACC()                                                               \
    u64t acc2[4][4];                                                             \
    _Pragma("unroll")                                                            \
    for (int p = 0; p < 4; p++)                                                  \
        _Pragma("unroll")                                                        \
        for (int c = 0; c < 4; c++) acc2[p][c] = 0ull;

// Staging-register STS for the A tile (transposed into shA[buf]).
#define STS_A(BUF)                                                               \
    _Pragma("unroll")                                                            \
    for (int it = 0; it < 2; it++) {                                             \
        int cc = ccA0 + it*8;                                                    \
        shA[BUF][cc+0][rrA] = a_reg[it].x; shA[BUF][cc+1][rrA] = a_reg[it].y;    \
        shA[BUF][cc+2][rrA] = a_reg[it].z; shA[BUF][cc+3][rrA] = a_reg[it].w;    \
    }

// -------------------------- in_proj GEMM: x = inputs @ W^T ------------------
// inputs: (ROWS, DIN); W: (DD, DIN) row-major (contraction contiguous).
__global__ void __launch_bounds__(256) k_in_proj(const float* __restrict__ inp,
                                                 const float* __restrict__ w) {
    int n0 = blockIdx.x * 64;
    int r0 = blockIdx.y * 128;
    __shared__ float shA[2][16][128];
    __shared__ float shW[2][16][64];
    int tid = threadIdx.x;
    int tx = tid & 15, ty = tid >> 4;
    int rrA = tid & 127, ccA0 = (tid >> 7) * 4;
    int jrW = tid & 63,  ccW0 = (tid >> 6) * 4;
    ZERO_ACC()
    float4 a_reg[2]; float4 w_reg;

    const int NT = DIN / 16;                   // 4
    #pragma unroll
    for (int it = 0; it < 2; it++)
        a_reg[it] = *reinterpret_cast<const float4*>(
            &inp[(size_t)(r0+rrA)*DIN + ccA0 + it*8]);
    w_reg = *reinterpret_cast<const float4*>(&w[(size_t)(n0+jrW)*DIN + ccW0]);
    STS_A(0)
    shW[0][ccW0+0][jrW] = w_reg.x; shW[0][ccW0+1][jrW] = w_reg.y;
    shW[0][ccW0+2][jrW] = w_reg.z; shW[0][ccW0+3][jrW] = w_reg.w;
    __syncthreads();

    int cur = 0;
    for (int kt = 0; kt < NT; kt++) {
        if (kt + 1 < NT) {
            int c0 = (kt + 1) * 16;
            #pragma unroll
            for (int it = 0; it < 2; it++)
                a_reg[it] = *reinterpret_cast<const float4*>(
                    &inp[(size_t)(r0+rrA)*DIN + c0 + ccA0 + it*8]);
            w_reg = *reinterpret_cast<const float4*>(
                &w[(size_t)(n0+jrW)*DIN + c0 + ccW0]);
        }
        GEMM_INNER2(shA[cur], shW[cur])
        if (kt + 1 < NT) {
            int nxt = cur ^ 1;
            STS_A(nxt)
            shW[nxt][ccW0+0][jrW] = w_reg.x; shW[nxt][ccW0+1][jrW] = w_reg.y;
            shW[nxt][ccW0+2][jrW] = w_reg.z; shW[nxt][ccW0+3][jrW] = w_reg.w;
            __syncthreads();
            cur = nxt;
        }
    }
    #pragma unroll
    for (int p = 0; p < 4; p++) {
        float2 v0 = up2(acc2[p][0]), v1 = up2(acc2[p][1]);
        float2 v2 = up2(acc2[p][2]), v3 = up2(acc2[p][3]);
        int row = r0 + ty*8 + 2*p;
        float4 lo = make_float4(v0.x, v1.x, v2.x, v3.x);
        float4 hi = make_float4(v0.y, v1.y, v2.y, v3.y);
        *reinterpret_cast<float4*>(&g_x[(size_t) row   *DD + n0 + tx*4]) = lo;
        *reinterpret_cast<float4*>(&g_x[(size_t)(row+1)*DD + n0 + tx*4]) = hi;
    }
}

// -------------------------- projection GEMM + ar_u + residual --------------
// x2[row,o] = x[row,o] + sum_{j,d} Uc[row,(j,d)] * W_j[d,o]
//                      + sum_{i<3}  h[b,s-i,d]   * Mu_i[d,o]
__global__ void __launch_bounds__(256) k_proj(const float* __restrict__ mp,
                                              const float* __restrict__ mm,
                                              const float* __restrict__ mu) {
    int o0 = blockIdx.x * 64;
    int r0 = blockIdx.y * 128;
    __shared__ float shA[2][16][128];
    __shared__ float shW[2][16][64];
    int tid = threadIdx.x;
    int tx = tid & 15, ty = tid >> 4;
    int rrA = tid & 127, ccA0 = (tid >> 7) * 4;     // A loader coords
    int wr = tid >> 4,  wc = (tid & 15) * 4;        // W loader coords (direct)
    ZERO_ACC()
    float4 a_reg[2]; float4 w_reg;

    // ---- main phase: contraction over Uc, NT1 = 1024 tiles
    const int NT1 = CDIM / 16;
    // fetch tile 0
    #pragma unroll
    for (int it = 0; it < 2; it++)
        a_reg[it] = *reinterpret_cast<const float4*>(
            &g_Uc[(size_t)(r0+rrA)*CDIM + ccA0 + it*8]);
    w_reg = *reinterpret_cast<const float4*>(&mp[(size_t)wr*DD + o0 + wc]);
    STS_A(0)
    *reinterpret_cast<float4*>(&shW[0][wr][wc]) = w_reg;
    __syncthreads();

    int cur = 0;
    for (int kt = 0; kt < NT1; kt++) {
        if (kt + 1 < NT1) {
            int c0 = (kt + 1) * 16;
            #pragma unroll
            for (int it = 0; it < 2; it++)
                a_reg[it] = *reinterpret_cast<const float4*>(
                    &g_Uc[(size_t)(r0+rrA)*CDIM + c0 + ccA0 + it*8]);
            int jj = c0 >> 9, dbase = c0 & 511;
            const float* wbase = (jj < 16 ? mp + (size_t)jj*DD*DD
                                          : mm + (size_t)(jj-16)*DD*DD);
            w_reg = *reinterpret_cast<const float4*>(
                &wbase[(size_t)(dbase+wr)*DD + o0 + wc]);
        }
        GEMM_INNER2(shA[cur], shW[cur])
        if (kt + 1 < NT1) {
            int nxt = cur ^ 1;
            STS_A(nxt)
            *reinterpret_cast<float4*>(&shW[nxt][wr][wc]) = w_reg;
            __syncthreads();
            cur = nxt;
        }
    }

    // ---- tail phase: ar_u, 3*32 = 96 tiles (re-prime pipeline)
    __syncthreads();                           // protect buffers before refill
    {
        int row = r0 + rrA, b = row >> 10, s = row & 1023;
        #pragma unroll
        for (int it = 0; it < 2; it++)
            a_reg[it] = *reinterpret_cast<const float4*>(
                &g_h[(size_t)(b*SS + s)*DD + ccA0 + it*8]);   // i=0, c0=0
        w_reg = *reinterpret_cast<const float4*>(&mu[(size_t)wr*DD + o0 + wc]);
    }
    STS_A(0)
    *reinterpret_cast<float4*>(&shW[0][wr][wc]) = w_reg;
    __syncthreads();
    cur = 0;

    const int NT2 = KUU * (DD / 16);           // 96
    for (int kt = 0; kt < NT2; kt++) {
        if (kt + 1 < NT2) {
            int i  = (kt + 1) >> 5;
            int c0 = ((kt + 1) & 31) * 16;
            int row = r0 + rrA, b = row >> 10, s = row & 1023;
            #pragma unroll
            for (int it = 0; it < 2; it++) {
                a_reg[it] = make_float4(0.f, 0.f, 0.f, 0.f);
                if (s >= i)
                    a_reg[it] = *reinterpret_cast<const float4*>(
                        &g_h[(size_t)(b*SS + s - i)*DD + c0 + ccA0 + it*8]);
            }
            w_reg = *reinterpret_cast<const float4*>(
                &mu[(size_t)i*DD*DD + (size_t)(c0+wr)*DD + o0 + wc]);
        }
        GEMM_INNER2(shA[cur], shW[cur])
        if (kt + 1 < NT2) {
            int nxt = cur ^ 1;
            STS_A(nxt)
            *reinterpret_cast<float4*>(&shW[nxt][wr][wc]) = w_reg;
            __syncthreads();
            cur = nxt;
        }
    }

    #pragma unroll
    for (int p = 0; p < 4; p++) {
        float2 v0 = up2(acc2[p][0]), v1 = up2(acc2[p][1]);
        float2 v2 = up2(acc2[p][2]), v3 = up2(acc2[p][3]);
        int row = r0 + ty*8 + 2*p;
        int o   = o0 + tx*4;
        float4 x0 = *reinterpret_cast<const float4*>(&g_x[(size_t)row*DD + o]);
        float4 x1 = *reinterpret_cast<const float4*>(&g_x[(size_t)(row+1)*DD + o]);
        float4 r0v = make_float4(x0.x + v0.x, x0.y + v1.x, x0.z + v2.x, x0.w + v3.x);
        float4 r1v = make_float4(x1.x + v0.y, x1.y + v1.y, x1.z + v2.y, x1.w + v3.y);
        *reinterpret_cast<float4*>(&g_x2[(size_t)row*DD + o])     = r0v;
        *reinterpret_cast<float4*>(&g_x2[(size_t)(row+1)*DD + o]) = r1v;
    }
}

// -------------------------- fc1 + swiglu fused ------------------------------
// g[row,h] = y * silu(gate),  y = x2 @ w1[0:H].T,  gate = x2 @ w1[H:2H].T
// One CTA computes BOTH halves for h-range [n0, n0+64).
__global__ void __launch_bounds__(256) k_fc1sw(const float* __restrict__ w1) {
    int n0 = blockIdx.x * 64;
    int r0 = blockIdx.y * 128;
    __shared__ float shA [2][16][128];
    __shared__ float shWY[2][16][64];
    __shared__ float shWG[2][16][64];
    int tid = threadIdx.x;
    int tx = tid & 15, ty = tid >> 4;
    int rrA = tid & 127, ccA0 = (tid >> 7) * 4;
    int jrW = tid & 63,  ccW0 = (tid >> 6) * 4;     // W loader (transposed)
    u64t accY[4][4], accG[4][4];
    #pragma unroll
    for (int p = 0; p < 4; p++)
        #pragma unroll
        for (int c = 0; c < 4; c++) { accY[p][c] = 0ull; accG[p][c] = 0ull; }
    float4 a_reg[2]; float4 wy_reg, wg_reg;
    const float* w1g = w1 + (size_t)HH*DD;          // gate half

    const int NT = DD / 16;                    // 32
    #pragma unroll
    for (int it = 0; it < 2; it++)
        a_reg[it] = *reinterpret_cast<const float4*>(
            &g_x2[(size_t)(r0+rrA)*DD + ccA0 + it*8]);
    wy_reg = *reinterpret_cast<const float4*>(&w1 [(size_t)(n0+jrW)*DD + ccW0]);
    wg_reg = *reinterpret_cast<const float4*>(&w1g[(size_t)(n0+jrW)*DD + ccW0]);
    STS_A(0)
    shWY[0][ccW0+0][jrW] = wy_reg.x; shWY[0][ccW0+1][jrW] = wy_reg.y;
    shWY[0][ccW0+2][jrW] = wy_reg.z; shWY[0][ccW0+3][jrW] = wy_reg.w;
    shWG[0][ccW0+0][jrW] = wg_reg.x; shWG[0][ccW0+1][jrW] = wg_reg.y;
    shWG[0][ccW0+2][jrW] = wg_reg.z; shWG[0][ccW0+3][jrW] = wg_reg.w;
    __syncthreads();

    int cur = 0;
    for (int kt = 0; kt < NT; kt++) {
        if (kt + 1 < NT) {
            int c0 = (kt + 1) * 16;
            #pragma unroll
            for (int it = 0; it < 2; it++)
                a_reg[it] = *reinterpret_cast<const float4*>(
                    &g_x2[(size_t)(r0+rrA)*DD + c0 + ccA0 + it*8]);
            wy_reg = *reinterpret_cast<const float4*>(
                &w1 [(size_t)(n0+jrW)*DD + c0 + ccW0]);
            wg_reg = *reinterpret_cast<const float4*>(
                &w1g[(size_t)(n0+jrW)*DD + c0 + ccW0]);
        }
        GEMM_INNER2_DUAL(shA[cur], shWY[cur], shWG[cur])
        if (kt + 1 < NT) {
            int nxt = cur ^ 1;
            STS_A(nxt)
            shWY[nxt][ccW0+0][jrW] = wy_reg.x; shWY[nxt][ccW0+1][jrW] = wy_reg.y;
            shWY[nxt][ccW0+2][jrW] = wy_reg.z; shWY[nxt][ccW0+3][jrW] = wy_reg.w;
            shWG[nxt][ccW0+0][jrW] = wg_reg.x; shWG[nxt][ccW0+1][jrW] = wg_reg.y;
            shWG[nxt][ccW0+2][jrW] = wg_reg.z; shWG[nxt][ccW0+3][jrW] = wg_reg.w;
            __syncthreads();
            cur = nxt;
        }
    }
    #pragma unroll
    for (int p = 0; p < 4; p++) {
        float2 y0 = up2(accY[p][0]), y1 = up2(accY[p][1]);
        float2 y2 = up2(accY[p][2]), y3 = up2(accY[p][3]);
        float2 q0 = up2(accG[p][0]), q1 = up2(accG[p][1]);
        float2 q2 = up2(accG[p][2]), q3 = up2(accG[p][3]);
        int row = r0 + ty*8 + 2*p;
        float4 lo, hi;
        lo.x = y0.x * (q0.x / (1.f + __expf(-q0.x)));
        lo.y = y1.x * (q1.x / (1.f + __expf(-q1.x)));
        lo.z = y2.x * (q2.x / (1.f + __expf(-q2.x)));
        lo.w = y3.x * (q3.x / (1.f + __expf(-q3.x)));
        hi.x = y0.y * (q0.y / (1.f + __expf(-q0.y)));
        hi.y = y1.y * (q1.y / (1.f + __expf(-q1.y)));
        hi.z = y2.y * (q2.y / (1.f + __expf(-q2.y)));
        hi.w = y3.y * (q3.y / (1.f + __expf(-q3.y)));
        *reinterpret_cast<float4*>(&g_g[(size_t) row   *HH + n0 + tx*4]) = lo;
        *reinterpret_cast<float4*>(&g_g[(size_t)(row+1)*HH + n0 + tx*4]) = hi;
    }
}

// -------------------------- fc2 + double residual --------------------------
// x[row,o] = x2[row,o] + g @ fc2^T + x[row,o]   (g_x holds z = layer input)
__global__ void __launch_bounds__(256) k_fc2(const float* __restrict__ w2) {
    int o0 = blockIdx.x * 64;
    int r0 = blockIdx.y * 128;
    __shared__ float shA[2][16][128];
    __shared__ float shW[2][16][64];
    int tid = threadIdx.x;
    int tx = tid & 15, ty = tid >> 4;
    int rrA = tid & 127, ccA0 = (tid >> 7) * 4;
    int jrW = tid & 63,  ccW0 = (tid >> 6) * 4;
    ZERO_ACC()
    float4 a_reg[2]; float4 w_reg;

    const int NT = HH / 16;                    // 128
    #pragma unroll
    for (int it = 0; it < 2; it++)
        a_reg[it] = *reinterpret_cast<const float4*>(
            &g_g[(size_t)(r0+rrA)*HH + ccA0 + it*8]);
    w_reg = *reinterpret_cast<const float4*>(&w2[(size_t)(o0+jrW)*HH + ccW0]);
    STS_A(0)
    shW[0][ccW0+0][jrW] = w_reg.x; shW[0][ccW0+1][jrW] = w_reg.y;
    shW[0][ccW0+2][jrW] = w_reg.z; shW[0][ccW0+3][jrW] = w_reg.w;
    __syncthreads();

    int cur = 0;
    for (int kt = 0; kt < NT; kt++) {
        if (kt + 1 < NT) {
            int c0 = (kt + 1) * 16;
            #pragma unroll
            for (int it = 0; it < 2; it++)
                a_reg[it] = *reinterpret_cast<const float4*>(
                    &g_g[(size_t)(r0+rrA)*HH + c0 + ccA0 + it*8]);
            w_reg = *reinterpret_cast<const float4*>(
                &w2[(size_t)(o0+jrW)*HH + c0 + ccW0]);
        }
        GEMM_INNER2(shA[cur], shW[cur])
        if (kt + 1 < NT) {
            int nxt = cur ^ 1;
            STS_A(nxt)
            shW[nxt][ccW0+0][jrW] = w_reg.x; shW[nxt][ccW0+1][jrW] = w_reg.y;
            shW[nxt][ccW0+2][jrW] = w_reg.z; shW[nxt][ccW0+3][jrW] = w_reg.w;
            __syncthreads();
            cur = nxt;
        }
    }
    #pragma unroll
    for (int p = 0; p < 4; p++) {
        float2 v0 = up2(acc2[p][0]), v1 = up2(acc2[p][1]);
        float2 v2 = up2(acc2[p][2]), v3 = up2(acc2[p][3]);
        int row = r0 + ty*8 + 2*p;
        int o   = o0 + tx*4;
        float4 xa = *reinterpret_cast<const float4*>(&g_x [(size_t)row*DD + o]);
        float4 xb = *reinterpret_cast<const float4*>(&g_x2[(size_t)row*DD + o]);
        float4 ya = *reinterpret_cast<const float4*>(&g_x [(size_t)(row+1)*DD + o]);
        float4 yb = *reinterpret_cast<const float4*>(&g_x2[(size_t)(row+1)*DD + o]);
        float4 r0v = make_float4(v0.x + xb.x + xa.x, v1.x + xb.y + xa.y,
                                 v2.x + xb.z + xa.z, v3.x + xb.w + xa.w);
        float4 r1v = make_float4(v0.y + yb.x + ya.x, v1.y + yb.y + ya.y,
                                 v2.y + yb.z + ya.z, v3.y + yb.w + ya.w);
        *reinterpret_cast<float4*>(&g_x[(size_t)row*DD + o])     = r0v;
        *reinterpret_cast<float4*>(&g_x[(size_t)(row+1)*DD + o]) = r1v;
    }
}

// -------------------------- out_proj GEMM (accumulate over m) ---------------
// out[row, o<64] (+)= sum_d x[row,d] * w[o,d];  w: (DIN, DD) row-major.
__global__ void __launch_bounds__(256) k_out_proj(const float* __restrict__ w,
                                                  float* __restrict__ out,
                                                  int add) {
    int r0 = blockIdx.x * 128;                 // 16 blocks
    __shared__ float shA[2][16][128];
    __shared__ float shW[2][16][64];
    int tid = threadIdx.x;
    int tx = tid & 15, ty = tid >> 4;
    int rrA = tid & 127, ccA0 = (tid >> 7) * 4;
    int jrW = tid & 63,  ccW0 = (tid >> 6) * 4;
    ZERO_ACC()
    float4 a_reg[2]; float4 w_reg;

    const int NT = DD / 16;                    // 32
    #pragma unroll
    for (int it = 0; it < 2; it++)
        a_reg[it] = *reinterpret_cast<const float4*>(
            &g_x[(size_t)(r0+rrA)*DD + ccA0 + it*8]);
    w_reg = *reinterpret_cast<const float4*>(&w[(size_t)jrW*DD + ccW0]);
    STS_A(0)
    shW[0][ccW0+0][jrW] = w_reg.x; shW[0][ccW0+1][jrW] = w_reg.y;
    shW[0][ccW0+2][jrW] = w_reg.z; shW[0][ccW0+3][jrW] = w_reg.w;
    __syncthreads();

    int cur = 0;
    for (int kt = 0; kt < NT; kt++) {
        if (kt + 1 < NT) {
            int c0 = (kt + 1) * 16;
            #pragma unroll
            for (int it = 0; it < 2; it++)
                a_reg[it] = *reinterpret_cast<const float4*>(
                    &g_x[(size_t)(r0+rrA)*DD + c0 + ccA0 + it*8]);
            w_reg = *reinterpret_cast<const float4*>(
                &w[(size_t)jrW*DD + c0 + ccW0]);
        }
        GEMM_INNER2(shA[cur], shW[cur])
        if (kt + 1 < NT) {
            int nxt = cur ^ 1;
            STS_A(nxt)
            shW[nxt][ccW0+0][jrW] = w_reg.x; shW[nxt][ccW0+1][jrW] = w_reg.y;
            shW[nxt][ccW0+2][jrW] = w_reg.z; shW[nxt][ccW0+3][jrW] = w_reg.w;
            __syncthreads();
            cur = nxt;
        }
    }
    #pragma unroll
    for (int p = 0; p < 4; p++) {
        float2 v0 = up2(acc2[p][0]), v1 = up2(acc2[p][1]);
        float2 v2 = up2(acc2[p][2]), v3 = up2(acc2[p][3]);
        int row = r0 + ty*8 + 2*p;
        int o   = tx*4;
        float4 lo = make_float4(v0.x, v1.x, v2.x, v3.x);
        float4 hi = make_float4(v0.y, v1.y, v2.y, v3.y);
        if (add) {
            float4 p0 = *reinterpret_cast<const float4*>(&out[(size_t)row*DIN + o]);
            float4 p1 = *reinterpret_cast<const float4*>(&out[(size_t)(row+1)*DIN + o]);
            lo.x += p0.x; lo.y += p0.y; lo.z += p0.z; lo.w += p0.w;
            hi.x += p1.x; hi.y += p1.y; hi.z += p1.z; hi.w += p1.w;
        }
        *reinterpret_cast<float4*>(&out[(size_t) row   *DIN + o]) = lo;
        *reinterpret_cast<float4*>(&out[(size_t)(row+1)*DIN + o]) = hi;
    }
}

// ---------------------------------------------------------------------------
extern "C" void kernel_launch(void* const* d_in, const int* in_sizes, int n_in,
                              void* d_out, int out_size) {
    const float* inputs      = (const float*)d_in[0];
    const float* sigma       = (const float*)d_in[1];
    const float* phi         = (const float*)d_in[2];
    const float* in_proj_w   = (const float*)d_in[3];
    const float* rn_w        = (const float*)d_in[4];
    const float* M_u         = (const float*)d_in[5];
    const float* M_phi_plus  = (const float*)d_in[6];
    const float* M_phi_minus = (const float*)d_in[7];
    const float* fc1_w       = (const float*)d_in[8];
    const float* fc2_w       = (const float*)d_in[9];
    const float* out_proj_w  = (const float*)d_in[10];
    float* out = (float*)d_out;

    for (int m = 0; m < MM; m++) {
        k_in_proj<<<dim3(8, 16), 256>>>(inputs, in_proj_w + (size_t)m*DD*DIN);
        for (int l = 0; l < LL; l++) {
            int ml = m*LL + l;
            k_rmsnorm<<<ROWS, 256>>>(rn_w + ml*DD);
            k_conv<<<dim3(8, 8, 32), 256>>>(phi, sigma);
            k_proj<<<dim3(8, 16), 256>>>(M_phi_plus  + (size_t)ml*KK*DD*DD,
                                         M_phi_minus + (size_t)ml*KK*DD*DD,
                                         M_u         + (size_t)ml*KUU*DD*DD);
            k_fc1sw<<<dim3(32, 16), 256>>>(fc1_w + (size_t)ml*2*HH*DD);
            k_fc2<<<dim3(8, 16), 256>>>(fc2_w + (size_t)ml*DD*HH);
        }
        k_out_proj<<<16, 256>>>(out_proj_w + (size_t)m*DIN*DD, out, m);
    }
}

// round 16
// speedup vs baseline: 1.1617x; 1.1617x over previous
#include <cuda_runtime.h>
#include <math.h>

// ---------------------------------------------------------------------------
// ResidualSTU  (B=2, S=1024, D_IN=64, D=512, K=16, KU=3, L=2, M=2, H=2048)
//
// FFT-free restructuring + even/odd conv split + fused epilogues (see R4-R6).
// R7-R15: 64-row tiles for proj/fc2/in/out (grid 256, >=2 CTA/SM) + coalesced
// A/W tile loaders (row=tid>>2) with stride-68 padded smem.
// Designed against measured R7 ncu: occ=12.5%, issue=27%, L1TEX=49.6%.
// ---------------------------------------------------------------------------

#define BB   2
#define SS   1024
#define DIN  64
#define DD   512
#define KK   16
#define KUU  3
#define LL   2
#define MM   2
#define HH   2048
#define J2K  32
#define ROWS (BB*SS)          // 2048
#define CDIM (J2K*DD)         // 16384
#define EPSV 1e-5f
#define SAPAD 68              // 64-row smem tile stride (pad vs bank conflicts)
#define SAPAD128 132          // 128-row smem tile stride

// -------------------------- device scratch (no allocs allowed) -------------
__device__ float g_x [ROWS*DD];
__device__ float g_h [ROWS*DD];
__device__ float g_x2[ROWS*DD];
__device__ float g_Uc[ROWS*CDIM];
__device__ float g_g [ROWS*HH];

// -------------------------- f32x2 packed helpers ---------------------------
typedef unsigned long long u64t;

__device__ __forceinline__ u64t pk2(float x, float y) {
    u64t r; asm("mov.b64 %0, {%1,%2};" : "=l"(r) : "f"(x), "f"(y)); return r;
}
__device__ __forceinline__ void fma2(u64t& d, u64t a, u64t b) {
    asm("fma.rn.f32x2 %0, %1, %2, %0;" : "+l"(d) : "l"(a), "l"(b));
}
__device__ __forceinline__ float2 up2(u64t v) {
    float2 r; asm("mov.b64 {%0,%1}, %2;" : "=f"(r.x), "=f"(r.y) : "l"(v)); return r;
}

// -------------------------- rmsnorm ----------------------------------------
__global__ void k_rmsnorm(const float* __restrict__ w) {
    int row = blockIdx.x;
    int tid = threadIdx.x;                    // 256 threads
    const float* xr = g_x + row*DD;
    float v0 = xr[tid], v1 = xr[tid + 256];
    float s = v0*v0 + v1*v1;
    __shared__ float red[8];
    #pragma unroll
    for (int off = 16; off; off >>= 1) s += __shfl_xor_sync(0xffffffffu, s, off);
    if ((tid & 31) == 0) red[tid >> 5] = s;
    __syncthreads();
    if (tid < 8) {
        float t = red[tid];
        #pragma unroll
        for (int off = 4; off; off >>= 1) t += __shfl_xor_sync(0xffu, t, off);
        if (tid == 0) red[0] = t;
    }
    __syncthreads();
    float scale = rsqrtf(red[0] * (1.f/DD) + EPSV);
    g_h[row*DD + tid]       = v0*scale*w[tid];
    g_h[row*DD + tid + 256] = v1*scale*w[tid + 256];
}

// -------------------------- causal Toeplitz conv (even/odd fused) ----------
__global__ void __launch_bounds__(256) k_conv(const float* __restrict__ phi,
                                              const float* __restrict__ sigma) {
    int d0 = blockIdx.x * 64;
    int s0 = blockIdx.y * 128;
    int bj = blockIdx.z;                      // 0..31
    int b  = bj >> 4;
    int k  = bj & 15;

    __shared__ float sh_h[2][16][64];
    __shared__ float sh_c[2][144];

    int tid = threadIdx.x;
    int tx = tid & 15, ty = tid >> 4;
    int hr = tid >> 4, hc = (tid & 15) * 4;
    u64t accE[4][4], accO[4][4];
    #pragma unroll
    for (int p = 0; p < 4; p++)
        #pragma unroll
        for (int c = 0; c < 4; c++) { accE[p][c] = 0ull; accO[p][c] = 0ull; }

    const float* hb = g_h + b*SS*DD;
    int NT = (s0 + 128) >> 4;

    float4 h_reg; float c_reg = 0.f;
    h_reg = *reinterpret_cast<const float4*>(&hb[hr*DD + d0 + hc]);
    if (tid < 144) {
        int tau = s0 - 15 + tid;
        c_reg = (tau >= 0 && tau < SS) ? phi[tau*KK + k] : 0.f;
    }
    *reinterpret_cast<float4*>(&sh_h[0][hr][hc]) = h_reg;
    if (tid < 144) sh_c[0][tid] = c_reg;
    __syncthreads();

    int cur = 0;
    for (int kt = 0; kt < NT; kt++) {
        if (kt + 1 < NT) {
            int t0 = (kt + 1) << 4;
            h_reg = *reinterpret_cast<const float4*>(&hb[(t0+hr)*DD + d0 + hc]);
            if (tid < 144) {
                int tau = s0 - t0 - 15 + tid;
                c_reg = (tau >= 0 && tau < SS) ? phi[tau*KK + k] : 0.f;
            }
        }
        #pragma unroll
        for (int tt = 0; tt < 16; tt++) {
            int base = ty*8 + 15 - tt;
            u64t a0 = pk2(sh_c[cur][base+0], sh_c[cur][base+1]);
            u64t a1 = pk2(sh_c[cur][base+2], sh_c[cur][base+3]);
            u64t a2 = pk2(sh_c[cur][base+4], sh_c[cur][base+5]);
            u64t a3 = pk2(sh_c[cur][base+6], sh_c[cur][base+7]);
            float4 bv = *reinterpret_cast<const float4*>(&sh_h[cur][tt][tx*4]);
            u64t b0 = pk2(bv.x, bv.x), b1 = pk2(bv.y, bv.y);
            u64t b2 = pk2(bv.z, bv.z), b3 = pk2(bv.w, bv.w);
            if ((tt & 1) == 0) {
                fma2(accE[0][0], a0, b0); fma2(accE[0][1], a0, b1);
                fma2(accE[0][2], a0, b2); fma2(accE[0][3], a0, b3);
                fma2(accE[1][0], a1, b0); fma2(accE[1][1], a1, b1);
                fma2(accE[1][2], a1, b2); fma2(accE[1][3], a1, b3);
                fma2(accE[2][0], a2, b0); fma2(accE[2][1], a2, b1);
                fma2(accE[2][2], a2, b2); fma2(accE[2][3], a2, b3);
                fma2(accE[3][0], a3, b0); fma2(accE[3][1], a3, b1);
                fma2(accE[3][2], a3, b2); fma2(accE[3][3], a3, b3);
            } else {
                fma2(accO[0][0], a0, b0); fma2(accO[0][1], a0, b1);
                fma2(accO[0][2], a0, b2); fma2(accO[0][3], a0, b3);
                fma2(accO[1][0], a1, b0); fma2(accO[1][1], a1, b1);
                fma2(accO[1][2], a1, b2); fma2(accO[1][3], a1, b3);
                fma2(accO[2][0], a2, b0); fma2(accO[2][1], a2, b1);
                fma2(accO[2][2], a2, b2); fma2(accO[2][3], a2, b3);
                fma2(accO[3][0], a3, b0); fma2(accO[3][1], a3, b1);
                fma2(accO[3][2], a3, b2); fma2(accO[3][3], a3, b3);
            }
        }
        if (kt + 1 < NT) {
            int nxt = cur ^ 1;
            *reinterpret_cast<float4*>(&sh_h[nxt][hr][hc]) = h_reg;
            if (tid < 144) sh_c[nxt][tid] = c_reg;
            __syncthreads();
            cur = nxt;
        }
    }

    float s4 = sqrtf(sqrtf(sigma[k]));
    #pragma unroll
    for (int p = 0; p < 4; p++) {
        float2 e0 = up2(accE[p][0]), e1 = up2(accE[p][1]);
        float2 e2 = up2(accE[p][2]), e3 = up2(accE[p][3]);
        float2 o0 = up2(accO[p][0]), o1 = up2(accO[p][1]);
        float2 o2 = up2(accO[p][2]), o3 = up2(accO[p][3]);
        int sA = s0 + ty*8 + 2*p;
        float4 up_lo = make_float4((e0.x+o0.x)*s4, (e1.x+o1.x)*s4,
                                   (e2.x+o2.x)*s4, (e3.x+o3.x)*s4);
        float4 up_hi = make_float4((e0.y+o0.y)*s4, (e1.y+o1.y)*s4,
                                   (e2.y+o2.y)*s4, (e3.y+o3.y)*s4);
        float4 um_lo = make_float4((e0.x-o0.x)*s4, (e1.x-o1.x)*s4,
                                   (e2.x-o2.x)*s4, (e3.x-o3.x)*s4);
        float4 um_hi = make_float4((o0.y-e0.y)*s4, (o1.y-e1.y)*s4,
                                   (o2.y-e2.y)*s4, (o3.y-e3.y)*s4);
        size_t rl = ((size_t)(b*SS + sA    )*J2K);
        size_t rh = ((size_t)(b*SS + sA + 1)*J2K);
        *reinterpret_cast<float4*>(&g_Uc[(rl + k     )*DD + d0 + tx*4]) = up_lo;
        *reinterpret_cast<float4*>(&g_Uc[(rh + k     )*DD + d0 + tx*4]) = up_hi;
        *reinterpret_cast<float4*>(&g_Uc[(rl + k + 16)*DD + d0 + tx*4]) = um_lo;
        *reinterpret_cast<float4*>(&g_Uc[(rh + k + 16)*DD + d0 + tx*4]) = um_hi;
    }
}

// ---- 64-row GEMM machinery (256 threads, 2-pair x 4 microtile) ------------
#define GEMM_INNER64(SHA, SHW)                                                   \
    _Pragma("unroll")                                                            \
    for (int tt = 0; tt < 16; tt++) {                                            \
        u64t a01 = *reinterpret_cast<const u64t*>(&SHA[tt][ty*4+0]);             \
        u64t a23 = *reinterpret_cast<const u64t*>(&SHA[tt][ty*4+2]);             \
        float4 w4 = *reinterpret_cast<const float4*>(&SHW[tt][tx*4]);            \
        u64t b0 = pk2(w4.x, w4.x), b1 = pk2(w4.y, w4.y);                         \
        u64t b2 = pk2(w4.z, w4.z), b3 = pk2(w4.w, w4.w);                         \
        fma2(acc2[0][0], a01, b0); fma2(acc2[0][1], a01, b1);                    \
        fma2(acc2[0][2], a01, b2); fma2(acc2[0][3], a01, b3);                    \
        fma2(acc2[1][0], a23, b0); fma2(acc2[1][1], a23, b1);                    \
        fma2(acc2[1][2], a23, b2); fma2(acc2[1][3], a23, b3);                    \
    }

#define ZERO_ACC64()                                                             \
    u64t acc2[2][4];                                                             \
    _Pragma("unroll")                                                            \
    for (int p = 0; p < 2; p++)                                                  \
        _Pragma("unroll")                                                        \
        for (int c = 0; c < 4; c++) acc2[p][c] = 0ull;

// A-tile STS (64 rows, transposed, coalesced-load layout: rA=tid>>2, cA=(tid&3)*4)
#define STS_A64(BUF)                                                             \
    do {                                                                         \
        shA[BUF][cA+0][rA] = a_reg.x; shA[BUF][cA+1][rA] = a_reg.y;              \
        shA[BUF][cA+2][rA] = a_reg.z; shA[BUF][cA+3][rA] = a_reg.w;              \
    } while (0)

// W-tile STS (transposed W loaders: rW=tid>>2, cW=(tid&3)*4)
#define STS_WT(ARR, BUF, REG)                                                    \
    do {                                                                         \
        ARR[BUF][cW+0][rW] = REG.x; ARR[BUF][cW+1][rW] = REG.y;                  \
        ARR[BUF][cW+2][rW] = REG.z; ARR[BUF][cW+3][rW] = REG.w;                  \
    } while (0)

// -------------------------- in_proj GEMM: x = inputs @ W^T ------------------
__global__ void __launch_bounds__(256) k_in_proj(const float* __restrict__ inp,
                                                 const float* __restrict__ w) {
    int n0 = blockIdx.x * 64;
    int r0 = blockIdx.y * 64;
    __shared__ float shA[2][16][SAPAD];
    __shared__ float shW[2][16][SAPAD];
    int tid = threadIdx.x;
    int tx = tid & 15, ty = tid >> 4;
    int rA = tid >> 2, cA = (tid & 3) * 4;
    int rW = tid >> 2, cW = (tid & 3) * 4;
    ZERO_ACC64()
    float4 a_reg, w_reg;

    const int NT = DIN / 16;                   // 4
    a_reg = *reinterpret_cast<const float4*>(&inp[(size_t)(r0+rA)*DIN + cA]);
    w_reg = *reinterpret_cast<const float4*>(&w[(size_t)(n0+rW)*DIN + cW]);
    STS_A64(0); STS_WT(shW, 0, w_reg);
    __syncthreads();

    int cur = 0;
    for (int kt = 0; kt < NT; kt++) {
        if (kt + 1 < NT) {
            int c0 = (kt + 1) * 16;
            a_reg = *reinterpret_cast<const float4*>(
                &inp[(size_t)(r0+rA)*DIN + c0 + cA]);
            w_reg = *reinterpret_cast<const float4*>(
                &w[(size_t)(n0+rW)*DIN + c0 + cW]);
        }
        GEMM_INNER64(shA[cur], shW[cur])
        if (kt + 1 < NT) {
            int nxt = cur ^ 1;
            STS_A64(nxt); STS_WT(shW, nxt, w_reg);
            __syncthreads();
            cur = nxt;
        }
    }
    #pragma unroll
    for (int p = 0; p < 2; p++) {
        float2 v0 = up2(acc2[p][0]), v1 = up2(acc2[p][1]);
        float2 v2 = up2(acc2[p][2]), v3 = up2(acc2[p][3]);
        int row = r0 + ty*4 + 2*p;
        float4 lo = make_float4(v0.x, v1.x, v2.x, v3.x);
        float4 hi = make_float4(v0.y, v1.y, v2.y, v3.y);
        *reinterpret_cast<float4*>(&g_x[(size_t) row   *DD + n0 + tx*4]) = lo;
        *reinterpret_cast<float4*>(&g_x[(size_t)(row+1)*DD + n0 + tx*4]) = hi;
    }
}

// -------------------------- projection GEMM + ar_u + residual --------------
__global__ void __launch_bounds__(256) k_proj(const float* __restrict__ mp,
                                              const float* __restrict__ mm,
                                              const float* __restrict__ mu) {
    int o0 = blockIdx.x * 64;
    int r0 = blockIdx.y * 64;
    __shared__ float shA[2][16][SAPAD];
    __shared__ float shW[2][16][SAPAD];
    int tid = threadIdx.x;
    int tx = tid & 15, ty = tid >> 4;
    int rA = tid >> 2, cA = (tid & 3) * 4;
    int wr = tid >> 4, wc = (tid & 15) * 4;   // W loader (direct, already coalesced)
    ZERO_ACC64()
    float4 a_reg, w_reg;

    // ---- main phase: contraction over Uc
    const int NT1 = CDIM / 16;
    a_reg = *reinterpret_cast<const float4*>(&g_Uc[(size_t)(r0+rA)*CDIM + cA]);
    w_reg = *reinterpret_cast<const float4*>(&mp[(size_t)wr*DD + o0 + wc]);
    STS_A64(0);
    *reinterpret_cast<float4*>(&shW[0][wr][wc]) = w_reg;
    __syncthreads();

    int cur = 0;
    for (int kt = 0; kt < NT1; kt++) {
        if (kt + 1 < NT1) {
            int c0 = (kt + 1) * 16;
            a_reg = *reinterpret_cast<const float4*>(
                &g_Uc[(size_t)(r0+rA)*CDIM + c0 + cA]);
            int jj = c0 >> 9, dbase = c0 & 511;
            const float* wbase = (jj < 16 ? mp + (size_t)jj*DD*DD
                                          : mm + (size_t)(jj-16)*DD*DD);
            w_reg = *reinterpret_cast<const float4*>(
                &wbase[(size_t)(dbase+wr)*DD + o0 + wc]);
        }
        GEMM_INNER64(shA[cur], shW[cur])
        if (kt + 1 < NT1) {
            int nxt = cur ^ 1;
            STS_A64(nxt);
            *reinterpret_cast<float4*>(&shW[nxt][wr][wc]) = w_reg;
            __syncthreads();
            cur = nxt;
        }
    }

    // ---- tail phase: ar_u (re-prime pipeline)
    __syncthreads();
    {
        int row = r0 + rA, b = row >> 10, s = row & 1023;
        a_reg = *reinterpret_cast<const float4*>(
            &g_h[(size_t)(b*SS + s)*DD + cA]);            // i=0, c0=0
        w_reg = *reinterpret_cast<const float4*>(&mu[(size_t)wr*DD + o0 + wc]);
    }
    STS_A64(0);
    *reinterpret_cast<float4*>(&shW[0][wr][wc]) = w_reg;
    __syncthreads();
    cur = 0;

    const int NT2 = KUU * (DD / 16);           // 96
    for (int kt = 0; kt < NT2; kt++) {
        if (kt + 1 < NT2) {
            int i  = (kt + 1) >> 5;
            int c0 = ((kt + 1) & 31) * 16;
            int row = r0 + rA, b = row >> 10, s = row & 1023;
            a_reg = make_float4(0.f, 0.f, 0.f, 0.f);
            if (s >= i)
                a_reg = *reinterpret_cast<const float4*>(
                    &g_h[(size_t)(b*SS + s - i)*DD + c0 + cA]);
            w_reg = *reinterpret_cast<const float4*>(
                &mu[(size_t)i*DD*DD + (size_t)(c0+wr)*DD + o0 + wc]);
        }
        GEMM_INNER64(shA[cur], shW[cur])
        if (kt + 1 < NT2) {
            int nxt = cur ^ 1;
            STS_A64(nxt);
            *reinterpret_cast<float4*>(&shW[nxt][wr][wc]) = w_reg;
            __syncthreads();
            cur = nxt;
        }
    }

    #pragma unroll
    for (int p = 0; p < 2; p++) {
        float2 v0 = up2(acc2[p][0]), v1 = up2(acc2[p][1]);
        float2 v2 = up2(acc2[p][2]), v3 = up2(acc2[p][3]);
        int row = r0 + ty*4 + 2*p;
        int o   = o0 + tx*4;
        float4 x0 = *reinterpret_cast<const float4*>(&g_x[(size_t)row*DD + o]);
        float4 x1 = *reinterpret_cast<const float4*>(&g_x[(size_t)(row+1)*DD + o]);
        float4 r0v = make_float4(x0.x + v0.x, x0.y + v1.x, x0.z + v2.x, x0.w + v3.x);
        float4 r1v = make_float4(x1.x + v0.y, x1.y + v1.y, x1.z + v2.y, x1.w + v3.y);
        *reinterpret_cast<float4*>(&g_x2[(size_t)row*DD + o])     = r0v;
        *reinterpret_cast<float4*>(&g_x2[(size_t)(row+1)*DD + o]) = r1v;
    }
}

// -------------------------- fc1 + swiglu fused (128-row tiles) --------------
#define GEMM_INNER128_DUAL(SHA, SHWY, SHWG)                                      \
    _Pragma("unroll")                                                            \
    for (int tt = 0; tt < 16; tt++) {                                            \
        u64t a0 = *reinterpret_cast<const u64t*>(&SHA[tt][ty*8+0]);              \
        u64t a1 = *reinterpret_cast<const u64t*>(&SHA[tt][ty*8+2]);              \
        u64t a2 = *reinterpret_cast<const u64t*>(&SHA[tt][ty*8+4]);              \
        u64t a3 = *reinterpret_cast<const u64t*>(&SHA[tt][ty*8+6]);              \
        float4 wy = *reinterpret_cast<const float4*>(&SHWY[tt][tx*4]);           \
        float4 wg = *reinterpret_cast<const float4*>(&SHWG[tt][tx*4]);           \
        u64t y0 = pk2(wy.x, wy.x), y1 = pk2(wy.y, wy.y);                         \
        u64t y2 = pk2(wy.z, wy.z), y3 = pk2(wy.w, wy.w);                         \
        u64t g0 = pk2(wg.x, wg.x), g1 = pk2(wg.y, wg.y);                         \
        u64t g2 = pk2(wg.z, wg.z), g3 = pk2(wg.w, wg.w);                         \
        fma2(accY[0][0], a0, y0); fma2(accY[0][1], a0, y1);                      \
        fma2(accY[0][2], a0, y2); fma2(accY[0][3], a0, y3);                      \
        fma2(accY[1][0], a1, y0); fma2(accY[1][1], a1, y1);                      \
        fma2(accY[1][2], a1, y2); fma2(accY[1][3], a1, y3);                      \
        fma2(accY[2][0], a2, y0); fma2(accY[2][1], a2, y1);                      \
        fma2(accY[2][2], a2, y2); fma2(accY[2][3], a2, y3);                      \
        fma2(accY[3][0], a3, y0); fma2(accY[3][1], a3, y1);                      \
        fma2(accY[3][2], a3, y2); fma2(accY[3][3], a3, y3);                      \
        fma2(accG[0][0], a0, g0); fma2(accG[0][1], a0, g1);                      \
        fma2(accG[0][2], a0, g2); fma2(accG[0][3], a0, g3);                      \
        fma2(accG[1][0], a1, g0); fma2(accG[1][1], a1, g1);                      \
        fma2(accG[1][2], a1, g2); fma2(accG[1][3], a1, g3);                      \
        fma2(accG[2][0], a2, g0); fma2(accG[2][1], a2, g1);                      \
        fma2(accG[2][2], a2, g2); fma2(accG[2][3], a2, g3);                      \
        fma2(accG[3][0], a3, g0); fma2(accG[3][1], a3, g1);                      \
        fma2(accG[3][2], a3, g2); fma2(accG[3][3], a3, g3);                      \
    }

#define STS_A128(BUF)                                                            \
    _Pragma("unroll")                                                            \
    for (int it = 0; it < 2; it++) {                                             \
        shA[BUF][cA+0][rA+it*64] = a_reg[it].x;                                  \
        shA[BUF][cA+1][rA+it*64] = a_reg[it].y;                                  \
        shA[BUF][cA+2][rA+it*64] = a_reg[it].z;                                  \
        shA[BUF][cA+3][rA+it*64] = a_reg[it].w;                                  \
    }

__global__ void __launch_bounds__(256) k_fc1sw(const float* __restrict__ w1) {
    int n0 = blockIdx.x * 64;
    int r0 = blockIdx.y * 128;
    __shared__ float shA [2][16][SAPAD128];
    __shared__ float shWY[2][16][SAPAD];
    __shared__ float shWG[2][16][SAPAD];
    int tid = threadIdx.x;
    int tx = tid & 15, ty = tid >> 4;
    int rA = tid >> 2, cA = (tid & 3) * 4;
    int rW = tid >> 2, cW = (tid & 3) * 4;
    u64t accY[4][4], accG[4][4];
    #pragma unroll
    for (int p = 0; p < 4; p++)
        #pragma unroll
        for (int c = 0; c < 4; c++) { accY[p][c] = 0ull; accG[p][c] = 0ull; }
    float4 a_reg[2]; float4 wy_reg, wg_reg;
    const float* w1g = w1 + (size_t)HH*DD;

    const int NT = DD / 16;                    // 32
    #pragma unroll
    for (int it = 0; it < 2; it++)
        a_reg[it] = *reinterpret_cast<const float4*>(
            &g_x2[(size_t)(r0+rA+it*64)*DD + cA]);
    wy_reg = *reinterpret_cast<const float4*>(&w1 [(size_t)(n0+rW)*DD + cW]);
    wg_reg = *reinterpret_cast<const float4*>(&w1g[(size_t)(n0+rW)*DD + cW]);
    STS_A128(0)
    STS_WT(shWY, 0, wy_reg); STS_WT(shWG, 0, wg_reg);
    __syncthreads();

    int cur = 0;
    for (int kt = 0; kt < NT; kt++) {
        if (kt + 1 < NT) {
            int c0 = (kt + 1) * 16;
            #pragma unroll
            for (int it = 0; it < 2; it++)
                a_reg[it] = *reinterpret_cast<const float4*>(
                    &g_x2[(size_t)(r0+rA+it*64)*DD + c0 + cA]);
            wy_reg = *reinterpret_cast<const float4*>(
                &w1 [(size_t)(n0+rW)*DD + c0 + cW]);
            wg_reg = *reinterpret_cast<const float4*>(
                &w1g[(size_t)(n0+rW)*DD + c0 + cW]);
        }
        GEMM_INNER128_DUAL(shA[cur], shWY[cur], shWG[cur])
        if (kt + 1 < NT) {
            int nxt = cur ^ 1;
            STS_A128(nxt)
            STS_WT(shWY, nxt, wy_reg); STS_WT(shWG, nxt, wg_reg);
            __syncthreads();
            cur = nxt;
        }
    }
    #pragma unroll
    for (int p = 0; p < 4; p++) {
        float2 y0 = up2(accY[p][0]), y1 = up2(accY[p][1]);
        float2 y2 = up2(accY[p][2]), y3 = up2(accY[p][3]);
        float2 q0 = up2(accG[p][0]), q1 = up2(accG[p][1]);
        float2 q2 = up2(accG[p][2]), q3 = up2(accG[p][3]);
        int row = r0 + ty*8 + 2*p;
        float4 lo, hi;
        lo.x = y0.x * (q0.x / (1.f + __expf(-q0.x)));
        lo.y = y1.x * (q1.x / (1.f + __expf(-q1.x)));
        lo.z = y2.x * (q2.x / (1.f + __expf(-q2.x)));
        lo.w = y3.x * (q3.x / (1.f + __expf(-q3.x)));
        hi.x = y0.y * (q0.y / (1.f + __expf(-q0.y)));
        hi.y = y1.y * (q1.y / (1.f + __expf(-q1.y)));
        hi.z = y2.y * (q2.y / (1.f + __expf(-q2.y)));
        hi.w = y3.y * (q3.y / (1.f + __expf(-q3.y)));
        *reinterpret_cast<float4*>(&g_g[(size_t) row   *HH + n0 + tx*4]) = lo;
        *reinterpret_cast<float4*>(&g_g[(size_t)(row+1)*HH + n0 + tx*4]) = hi;
    }
}

// -------------------------- fc2 + double residual (64-row tiles) ------------
__global__ void __launch_bounds__(256) k_fc2(const float* __restrict__ w2) {
    int o0 = blockIdx.x * 64;
    int r0 = blockIdx.y * 64;
    __shared__ float shA[2][16][SAPAD];
    __shared__ float shW[2][16][SAPAD];
    int tid = threadIdx.x;
    int tx = tid & 15, ty = tid >> 4;
    int rA = tid >> 2, cA = (tid & 3) * 4;
    int rW = tid >> 2, cW = (tid & 3) * 4;
    ZERO_ACC64()
    float4 a_reg, w_reg;

    const int NT = HH / 16;                    // 128
    a_reg = *reinterpret_cast<const float4*>(&g_g[(size_t)(r0+rA)*HH + cA]);
    w_reg = *reinterpret_cast<const float4*>(&w2[(size_t)(o0+rW)*HH + cW]);
    STS_A64(0); STS_WT(shW, 0, w_reg);
    __syncthreads();

    int cur = 0;
    for (int kt = 0; kt < NT; kt++) {
        if (kt + 1 < NT) {
            int c0 = (kt + 1) * 16;
            a_reg = *reinterpret_cast<const float4*>(
                &g_g[(size_t)(r0+rA)*HH + c0 + cA]);
            w_reg = *reinterpret_cast<const float4*>(
                &w2[(size_t)(o0+rW)*HH + c0 + cW]);
        }
        GEMM_INNER64(shA[cur], shW[cur])
        if (kt + 1 < NT) {
            int nxt = cur ^ 1;
            STS_A64(nxt); STS_WT(shW, nxt, w_reg);
            __syncthreads();
            cur = nxt;
        }
    }
    #pragma unroll
    for (int p = 0; p < 2; p++) {
        float2 v0 = up2(acc2[p][0]), v1 = up2(acc2[p][1]);
        float2 v2 = up2(acc2[p][2]), v3 = up2(acc2[p][3]);
        int row = r0 + ty*4 + 2*p;
        int o   = o0 + tx*4;
        float4 xa = *reinterpret_cast<const float4*>(&g_x [(size_t)row*DD + o]);
        float4 xb = *reinterpret_cast<const float4*>(&g_x2[(size_t)row*DD + o]);
        float4 ya = *reinterpret_cast<const float4*>(&g_x [(size_t)(row+1)*DD + o]);
        float4 yb = *reinterpret_cast<const float4*>(&g_x2[(size_t)(row+1)*DD + o]);
        float4 r0v = make_float4(v0.x + xb.x + xa.x, v1.x + xb.y + xa.y,
                                 v2.x + xb.z + xa.z, v3.x + xb.w + xa.w);
        float4 r1v = make_float4(v0.y + yb.x + ya.x, v1.y + yb.y + ya.y,
                                 v2.y + yb.z + ya.z, v3.y + yb.w + ya.w);
        *reinterpret_cast<float4*>(&g_x[(size_t)row*DD + o])     = r0v;
        *reinterpret_cast<float4*>(&g_x[(size_t)(row+1)*DD + o]) = r1v;
    }
}

// -------------------------- out_proj GEMM (64-row tiles) --------------------
__global__ void __launch_bounds__(256) k_out_proj(const float* __restrict__ w,
                                                  float* __restrict__ out,
                                                  int add) {
    int r0 = blockIdx.x * 64;                  // 32 blocks
    __shared__ float shA[2][16][SAPAD];
    __shared__ float shW[2][16][SAPAD];
    int tid = threadIdx.x;
    int tx = tid & 15, ty = tid >> 4;
    int rA = tid >> 2, cA = (tid & 3) * 4;
    int rW = tid >> 2, cW = (tid & 3) * 4;
    ZERO_ACC64()
    float4 a_reg, w_reg;

    const int NT = DD / 16;                    // 32
    a_reg = *reinterpret_cast<const float4*>(&g_x[(size_t)(r0+rA)*DD + cA]);
    w_reg = *reinterpret_cast<const float4*>(&w[(size_t)rW*DD + cW]);
    STS_A64(0); STS_WT(shW, 0, w_reg);
    __syncthreads();

    int cur = 0;
    for (int kt = 0; kt < NT; kt++) {
        if (kt + 1 < NT) {
            int c0 = (kt + 1) * 16;
            a_reg = *reinterpret_cast<const float4*>(
                &g_x[(size_t)(r0+rA)*DD + c0 + cA]);
            w_reg = *reinterpret_cast<const float4*>(
                &w[(size_t)rW*DD + c0 + cW]);
        }
        GEMM_INNER64(shA[cur], shW[cur])
        if (kt + 1 < NT) {
            int nxt = cur ^ 1;
            STS_A64(nxt); STS_WT(shW, nxt, w_reg);
            __syncthreads();
            cur = nxt;
        }
    }
    #pragma unroll
    for (int p = 0; p < 2; p++) {
        float2 v0 = up2(acc2[p][0]), v1 = up2(acc2[p][1]);
        float2 v2 = up2(acc2[p][2]), v3 = up2(acc2[p][3]);
        int row = r0 + ty*4 + 2*p;
        int o   = tx*4;
        float4 lo = make_float4(v0.x, v1.x, v2.x, v3.x);
        float4 hi = make_float4(v0.y, v1.y, v2.y, v3.y);
        if (add) {
            float4 p0 = *reinterpret_cast<const float4*>(&out[(size_t)row*DIN + o]);
            float4 p1 = *reinterpret_cast<const float4*>(&out[(size_t)(row+1)*DIN + o]);
            lo.x += p0.x; lo.y += p0.y; lo.z += p0.z; lo.w += p0.w;
            hi.x += p1.x; hi.y += p1.y; hi.z += p1.z; hi.w += p1.w;
        }
        *reinterpret_cast<float4*>(&out[(size_t) row   *DIN + o]) = lo;
        *reinterpret_cast<float4*>(&out[(size_t)(row+1)*DIN + o]) = hi;
    }
}

// ---------------------------------------------------------------------------
extern "C" void kernel_launch(void* const* d_in, const int* in_sizes, int n_in,
                              void* d_out, int out_size) {
    const float* inputs      = (const float*)d_in[0];
    const float* sigma       = (const float*)d_in[1];
    const float* phi         = (const float*)d_in[2];
    const float* in_proj_w   = (const float*)d_in[3];
    const float* rn_w        = (const float*)d_in[4];
    const float* M_u         = (const float*)d_in[5];
    const float* M_phi_plus  = (const float*)d_in[6];
    const float* M_phi_minus = (const float*)d_in[7];
    const float* fc1_w       = (const float*)d_in[8];
    const float* fc2_w       = (const float*)d_in[9];
    const float* out_proj_w  = (const float*)d_in[10];
    float* out = (float*)d_out;

    for (int m = 0; m < MM; m++) {
        k_in_proj<<<dim3(8, 32), 256>>>(inputs, in_proj_w + (size_t)m*DD*DIN);
        for (int l = 0; l < LL; l++) {
            int ml = m*LL + l;
            k_rmsnorm<<<ROWS, 256>>>(rn_w + ml*DD);
            k_conv<<<dim3(8, 8, 32), 256>>>(phi, sigma);
            k_proj<<<dim3(8, 32), 256>>>(M_phi_plus  + (size_t)ml*KK*DD*DD,
                                         M_phi_minus + (size_t)ml*KK*DD*DD,
                                         M_u         + (size_t)ml*KUU*DD*DD);
            k_fc1sw<<<dim3(32, 16), 256>>>(fc1_w + (size_t)ml*2*HH*DD);
            k_fc2<<<dim3(8, 32), 256>>>(fc2_w + (size_t)ml*DD*HH);
        }
        k_out_proj<<<32, 256>>>(out_proj_w + (size_t)m*DIN*DD, out, m);
    }
}